// round 15
// baseline (speedup 1.0000x reference)
#include <cuda_runtime.h>
#include <cuda_bf16.h>
#include <math.h>
#include <stdint.h>

// Problem constants
#define Bc   4
#define L1c  1024
#define L2c  512
#define Lc   1536
#define DPGc 2304
#define DEXc 1024
#define Hc   8
#define HKVc 4
#define DHc  256
#define SCALEc 0.0625f
#define QKVW 4096              // fused QKV width: 2048 q + 1024 k + 1024 v

// ---------------------------------------------------------------------------
// Scratch (device globals; allocation-free)
// ---------------------------------------------------------------------------
__device__ __align__(128) float g_qkv[(size_t)Bc * Lc * QKVW];       // fused QKV fp32
__device__ __align__(128) float g_scores[(size_t)Bc * Hc * Lc * Lc];

#define DECL_HL(T, name, count) \
    __device__ __align__(128) T name##_h[count]; \
    __device__ __align__(128) T name##_l[count];

DECL_HL(__nv_bfloat16, g_pg,  (size_t)Bc * L1c * DPGc)
DECL_HL(__nv_bfloat16, g_ex,  (size_t)Bc * L2c * DEXc)
DECL_HL(__nv_bfloat16, g_wc0, (size_t)QKVW * DPGc)     // cat(Wq0,Wk0,Wv0)
DECL_HL(__nv_bfloat16, g_wc1, (size_t)QKVW * DEXc)     // cat(Wq1,Wk1,Wv1)
DECL_HL(__nv_bfloat16, g_wo0, (size_t)DPGc * Hc * DHc)
DECL_HL(__nv_bfloat16, g_wo1, (size_t)DEXc * Hc * DHc)
DECL_HL(__nv_bfloat16, g_qb,  (size_t)Bc * Lc * Hc * DHc)
DECL_HL(__nv_bfloat16, g_kb,  (size_t)Bc * Lc * HKVc * DHc)
DECL_HL(__nv_bfloat16, g_vt,  (size_t)Bc * HKVc * DHc * Lc)   // V^T: [B*HKV, DH, L]
DECL_HL(__nv_bfloat16, g_p,   (size_t)Bc * Hc * Lc * Lc)
DECL_HL(__nv_bfloat16, g_attb,(size_t)Bc * Lc * Hc * DHc)

// ---------------------------------------------------------------------------
// PTX helpers (compute_103-safe: cp.async, ldmatrix, mma.sync only)
// ---------------------------------------------------------------------------
__device__ __forceinline__ uint32_t smem_u32(const void* p) {
    uint32_t a;
    asm("{ .reg .u64 t; cvta.to.shared.u64 t, %1; cvt.u32.u64 %0, t; }" : "=r"(a) : "l"(p));
    return a;
}
#define CP_ASYNC16(dst, src) \
    asm volatile("cp.async.cg.shared.global [%0], [%1], 16;" :: "r"(dst), "l"(src) : "memory")
#define CP_COMMIT() asm volatile("cp.async.commit_group;" ::: "memory")

#define LDMX4(r0, r1, r2, r3, addr) \
    asm volatile("ldmatrix.sync.aligned.m8n8.x4.shared.b16 {%0,%1,%2,%3}, [%4];" \
                 : "=r"(r0), "=r"(r1), "=r"(r2), "=r"(r3) : "r"(addr))

#define MMA16816(c, a, b0, b1) \
    asm volatile("mma.sync.aligned.m16n8k16.row.col.f32.bf16.bf16.f32 " \
                 "{%0,%1,%2,%3}, {%4,%5,%6,%7}, {%8,%9}, {%0,%1,%2,%3};" \
                 : "+f"((c)[0]), "+f"((c)[1]), "+f"((c)[2]), "+f"((c)[3]) \
                 : "r"((a)[0]), "r"((a)[1]), "r"((a)[2]), "r"((a)[3]), \
                   "r"(b0), "r"(b1))

// ---------------------------------------------------------------------------
// GEMM segment descriptor (one logical batched GEMM)
// ---------------------------------------------------------------------------
struct GSeg {
    const __nv_bfloat16 *Ah, *Al, *Bh, *Bl;
    float* C; const float* D;
    __nv_bfloat16 *Ch, *Cl;
    int M, N, K, lda, ldb, ldc, ldd;
    long sAo, sAi, sBo, sBi, sCo, sCi, sDo;
    int div_, rep;
    float alpha;
    int nx, ny;            // grid decomposition for flattened dispatch
};

// ---------------------------------------------------------------------------
// bf16x2-split GEMM body via mma.sync.  C = alpha * A @ B^T (+ D)
// Tiles 128x128x64, warp tile 64x32 (8 warps as 2m x 4n).
// 3-stage cp.async pipeline, single __syncthreads per k-tile,
// ks-level fragment double-buffering, SW128 swizzle, 256 threads.
// 3 compensation passes: Ah*Bh + Ah*Bl + Al*Bh, fp32 accumulate.
// OUTB=0: fp32 C (+D). OUTB=1: bf16 hi/lo split into Ch/Cl.
// ---------------------------------------------------------------------------
#define STAGE_BYTES 65536                    // 4 tiles x 16KB (Ah,Bh,Al,Bl)
#define NSTAGE 3
#define SMEM_BYTES  (NSTAGE * STAGE_BYTES + 1024)

template <int OUTB>
__device__ __forceinline__ void gemm_body(const GSeg& g, int bxi, int byi, int z,
                                          char* smem_raw)
{
    uint32_t sb0 = smem_u32(smem_raw);
    uint32_t sb  = (sb0 + 1023) & ~1023u;
    char* smem_al = smem_raw + (sb - sb0);

    int tid = threadIdx.x, wid = tid >> 5, lane = tid & 31;
    int wm = wid & 1, wn = wid >> 1;

    const __nv_bfloat16* Ahi = g.Ah;
    const __nv_bfloat16* Alo = g.Al;
    const __nv_bfloat16* Bhi = g.Bh;
    const __nv_bfloat16* Blo = g.Bl;
    float* C = g.C;
    const float* D = g.D;
    __nv_bfloat16* Ch = g.Ch;
    __nv_bfloat16* Cl = g.Cl;
    int lda = g.lda, ldb = g.ldb, ldc = g.ldc, ldd = g.ldd;
    int K = g.K;
    float alpha = g.alpha;

    int zo = z / g.div_, zi = z % g.div_;
    long aoff = (long)zo * g.sAo + (long)zi * g.sAi;
    long boff = (long)zo * g.sBo + (long)(zi / g.rep) * g.sBi;
    Ahi += aoff; Alo += aoff; Bhi += boff; Blo += boff;
    long coff = (long)zo * g.sCo + (long)zi * g.sCi;
    if (OUTB) { Ch += coff; Cl += coff; }
    else      { C += coff; if (D) D += (long)zo * g.sDo; }

    int bm = byi * 128;
    int bn = bxi * 128;

    float acc[4][4][4] = {};

    const int KT = K >> 6;

#define LOAD_STAGE(ktv)                                                        \
    do {                                                                       \
        uint32_t stb_ = sb + ((ktv) % NSTAGE) * STAGE_BYTES;                   \
        int k0_ = (ktv) << 6;                                                  \
        _Pragma("unroll")                                                      \
        for (int tile = 0; tile < 4; tile++) {                                 \
            const __nv_bfloat16* base =                                        \
                (tile == 0) ? Ahi : (tile == 1) ? Bhi : (tile == 2) ? Alo : Blo;\
            int ld = (tile & 1) ? ldb : lda;                                   \
            int rb = (tile & 1) ? bn : bm;                                     \
            _Pragma("unroll")                                                  \
            for (int j = 0; j < 4; j++) {                                      \
                int idx = j * 256 + tid;                                       \
                int row = idx >> 3, c = idx & 7;                               \
                const __nv_bfloat16* src = base + (long)(rb + row) * ld + k0_ + c * 8; \
                uint32_t doff = (uint32_t)(row * 128 + c * 16);                \
                doff ^= (doff >> 3) & 0x70;                                    \
                CP_ASYNC16(stb_ + tile * 16384 + doff, src);                   \
            }                                                                  \
        }                                                                      \
        CP_COMMIT();                                                           \
    } while (0)

    uint32_t ah[2][4][4], al[2][4][4], bh[2][4][2], bl[2][4][2];
#define LOAD_FRAGS(bi, ks_)                                                    \
    do {                                                                       \
        int arow0 = wm * 64 + (lane & 15);                                     \
        int ac    = 2 * (ks_) + (lane >> 4);                                   \
        _Pragma("unroll")                                                      \
        for (int mi = 0; mi < 4; mi++) {                                       \
            int r = arow0 + mi * 16;                                           \
            uint32_t off = (uint32_t)(r * 128 + ((ac ^ (r & 7)) << 4));        \
            LDMX4(ah[bi][mi][0], ah[bi][mi][1], ah[bi][mi][2], ah[bi][mi][3],  \
                  stb + off);                                                  \
            LDMX4(al[bi][mi][0], al[bi][mi][1], al[bi][mi][2], al[bi][mi][3],  \
                  stb + 32768 + off);                                          \
        }                                                                      \
        int bn0 = wn * 32 + ((lane >> 4) << 3) + (lane & 7);                   \
        int bcc = 2 * (ks_) + ((lane >> 3) & 1);                               \
        _Pragma("unroll")                                                      \
        for (int nj = 0; nj < 2; nj++) {                                       \
            int r = bn0 + nj * 16;                                             \
            uint32_t off = (uint32_t)(r * 128 + ((bcc ^ (r & 7)) << 4));       \
            uint32_t t0, t1, t2, t3;                                           \
            LDMX4(t0, t1, t2, t3, stb + 16384 + off);                          \
            bh[bi][2 * nj][0] = t0;     bh[bi][2 * nj][1] = t1;                \
            bh[bi][2 * nj + 1][0] = t2; bh[bi][2 * nj + 1][1] = t3;            \
            LDMX4(t0, t1, t2, t3, stb + 49152 + off);                          \
            bl[bi][2 * nj][0] = t0;     bl[bi][2 * nj][1] = t1;                \
            bl[bi][2 * nj + 1][0] = t2; bl[bi][2 * nj + 1][1] = t3;            \
        }                                                                      \
    } while (0)

    LOAD_STAGE(0);
    if (KT > 1) LOAD_STAGE(1);

    for (int kt = 0; kt < KT; kt++) {
        if (kt + 1 < KT) {
            asm volatile("cp.async.wait_group 1;" ::: "memory");
        } else {
            asm volatile("cp.async.wait_group 0;" ::: "memory");
        }
        __syncthreads();
        if (kt + 2 < KT) LOAD_STAGE(kt + 2);

        uint32_t stb = sb + (kt % NSTAGE) * STAGE_BYTES;

        LOAD_FRAGS(0, 0);
#pragma unroll
        for (int ks = 0; ks < 4; ks++) {
            int cur = ks & 1;
            if (ks < 3) LOAD_FRAGS((ks + 1) & 1, ks + 1);
#pragma unroll
            for (int mi = 0; mi < 4; mi++)
#pragma unroll
                for (int ni = 0; ni < 4; ni++) {
                    MMA16816(acc[mi][ni], ah[cur][mi], bh[cur][ni][0], bh[cur][ni][1]);
                    MMA16816(acc[mi][ni], ah[cur][mi], bl[cur][ni][0], bl[cur][ni][1]);
                    MMA16816(acc[mi][ni], al[cur][mi], bh[cur][ni][0], bh[cur][ni][1]);
                }
        }
    }
    __syncthreads();

    // ---- epilogue: regs -> SMEM (stride 132) -> coalesced GMEM ----
    float* Ct = (float*)smem_al;
    int tq = lane >> 2, tr2 = (lane & 3) * 2;
#pragma unroll
    for (int mi = 0; mi < 4; mi++)
#pragma unroll
        for (int ni = 0; ni < 4; ni++) {
            int r0 = wm * 64 + mi * 16 + tq;
            int cc = wn * 32 + ni * 8 + tr2;
            *(float2*)&Ct[r0 * 132 + cc] =
                make_float2(acc[mi][ni][0] * alpha, acc[mi][ni][1] * alpha);
            *(float2*)&Ct[(r0 + 8) * 132 + cc] =
                make_float2(acc[mi][ni][2] * alpha, acc[mi][ni][3] * alpha);
        }
    __syncthreads();

#pragma unroll
    for (int it = 0; it < 16; it++) {
        int r = it * 8 + wid;
        float4 v = *(float4*)&Ct[r * 132 + lane * 4];
        if (OUTB) {
            __nv_bfloat16 h0 = __float2bfloat16(v.x), h1 = __float2bfloat16(v.y);
            __nv_bfloat16 h2 = __float2bfloat16(v.z), h3 = __float2bfloat16(v.w);
            long base = (long)(bm + r) * ldc + bn + lane * 4;
            ((__nv_bfloat162*)(Ch + base))[0] = __nv_bfloat162(h0, h1);
            ((__nv_bfloat162*)(Ch + base))[1] = __nv_bfloat162(h2, h3);
            ((__nv_bfloat162*)(Cl + base))[0] =
                __nv_bfloat162(__float2bfloat16(v.x - __bfloat162float(h0)),
                               __float2bfloat16(v.y - __bfloat162float(h1)));
            ((__nv_bfloat162*)(Cl + base))[1] =
                __nv_bfloat162(__float2bfloat16(v.z - __bfloat162float(h2)),
                               __float2bfloat16(v.w - __bfloat162float(h3)));
        } else {
            if (D) {
                const float* dp = &D[(long)(bm + r) * ldd + bn + lane * 4];
                v.x += dp[0]; v.y += dp[1]; v.z += dp[2]; v.w += dp[3];
            }
            *(float4*)&C[(long)(bm + r) * ldc + bn + lane * 4] = v;
        }
    }
}

template <int OUTB>
__global__ void __launch_bounds__(256, 1) gemm_one(GSeg g)
{
    extern __shared__ char smem_raw[];
    gemm_body<OUTB>(g, blockIdx.x, blockIdx.y, blockIdx.z, smem_raw);
}

// Two independent GEMM segments in one flattened launch (tail packing).
template <int OUTB>
__global__ void __launch_bounds__(256, 1) gemm_pair(GSeg g0, GSeg g1, int split)
{
    extern __shared__ char smem_raw[];
    int f = blockIdx.x;
    if (f < split) {
        int x = f % g0.nx, r = f / g0.nx;
        gemm_body<OUTB>(g0, x, r % g0.ny, r / g0.ny, smem_raw);
    } else {
        f -= split;
        int x = f % g1.nx, r = f / g1.nx;
        gemm_body<OUTB>(g1, x, r % g1.ny, r / g1.ny, smem_raw);
    }
}

// ---------------------------------------------------------------------------
// Multi-segment fp32 -> bf16 hi/lo split (one launch, MLP=4/thread)
// ---------------------------------------------------------------------------
#define NSEG 10
struct CvtSegs {
    const float* x[NSEG];
    __nv_bfloat16* h[NSEG];
    __nv_bfloat16* l[NSEG];
    long start[NSEG + 1];
};

__global__ void cvt_multi_kernel(CvtSegs s)
{
    long base = (long)blockIdx.x * 1024 + threadIdx.x;
#pragma unroll
    for (int u = 0; u < 4; u++) {
        long i = base + u * 256;
        if (i >= s.start[NSEG]) return;
        int seg = 0;
#pragma unroll
        for (int j = 1; j < NSEG; j++) seg += (i >= s.start[j]);
        long off = i - s.start[seg];

        float4 v = ((const float4*)s.x[seg])[off];
        __nv_bfloat16 h0 = __float2bfloat16(v.x), h1 = __float2bfloat16(v.y);
        __nv_bfloat16 h2 = __float2bfloat16(v.z), h3 = __float2bfloat16(v.w);
        ((__nv_bfloat162*)s.h[seg])[off * 2 + 0] = __nv_bfloat162(h0, h1);
        ((__nv_bfloat162*)s.h[seg])[off * 2 + 1] = __nv_bfloat162(h2, h3);
        ((__nv_bfloat162*)s.l[seg])[off * 2 + 0] =
            __nv_bfloat162(__float2bfloat16(v.x - __bfloat162float(h0)),
                           __float2bfloat16(v.y - __bfloat162float(h1)));
        ((__nv_bfloat162*)s.l[seg])[off * 2 + 1] =
            __nv_bfloat162(__float2bfloat16(v.z - __bfloat162float(h2)),
                           __float2bfloat16(v.w - __bfloat162float(h3)));
    }
}

// ---------------------------------------------------------------------------
// Vectorized fused RoPE + split for q AND k from the fused QKV buffer.
// ---------------------------------------------------------------------------
__global__ void rope_cvt_kernel(const float* __restrict__ qkv,
                                const float* __restrict__ cosp, const float* __restrict__ sinp,
                                __nv_bfloat16* __restrict__ qh, __nv_bfloat16* __restrict__ ql,
                                __nv_bfloat16* __restrict__ kh, __nv_bfloat16* __restrict__ kl,
                                long total_q)
{
    long idx = (long)blockIdx.x * 256 + threadIdx.x;
    if (idx >= total_q) return;
    int  d   = (int)(idx & 31) * 4;
    long t   = idx >> 5;
    int  h12 = (int)(t % 12);
    long bl  = t / 12;

    float4 c4 = *(const float4*)&cosp[bl * 128 + d];
    float4 s4 = *(const float4*)&sinp[bl * 128 + d];

    const float* row = qkv + bl * QKVW;
    __nv_bfloat16 *dh, *dl;
    int colbase;
    if (h12 < 8) {
        colbase = h12 * DHc;
        long dbase = bl * (Hc * DHc) + h12 * DHc;
        dh = qh + dbase; dl = ql + dbase;
    } else {
        colbase = 2048 + (h12 - 8) * DHc;
        long dbase = bl * (HKVc * DHc) + (h12 - 8) * DHc;
        dh = kh + dbase; dl = kl + dbase;
    }
    float4 x1 = *(const float4*)&row[colbase + d];
    float4 x2 = *(const float4*)&row[colbase + d + 128];

    float o1x = x1.x * c4.x - x2.x * s4.x,  o2x = x2.x * c4.x + x1.x * s4.x;
    float o1y = x1.y * c4.y - x2.y * s4.y,  o2y = x2.y * c4.y + x1.y * s4.y;
    float o1z = x1.z * c4.z - x2.z * s4.z,  o2z = x2.z * c4.z + x1.z * s4.z;
    float o1w = x1.w * c4.w - x2.w * s4.w,  o2w = x2.w * c4.w + x1.w * s4.w;

    __nv_bfloat16 a0 = __float2bfloat16(o1x), a1 = __float2bfloat16(o1y);
    __nv_bfloat16 a2 = __float2bfloat16(o1z), a3 = __float2bfloat16(o1w);
    __nv_bfloat16 b0 = __float2bfloat16(o2x), b1 = __float2bfloat16(o2y);
    __nv_bfloat16 b2 = __float2bfloat16(o2z), b3 = __float2bfloat16(o2w);

    ((__nv_bfloat162*)(dh + d))[0]       = __nv_bfloat162(a0, a1);
    ((__nv_bfloat162*)(dh + d))[1]       = __nv_bfloat162(a2, a3);
    ((__nv_bfloat162*)(dh + d + 128))[0] = __nv_bfloat162(b0, b1);
    ((__nv_bfloat162*)(dh + d + 128))[1] = __nv_bfloat162(b2, b3);

    ((__nv_bfloat162*)(dl + d))[0] =
        __nv_bfloat162(__float2bfloat16(o1x - __bfloat162float(a0)),
                       __float2bfloat16(o1y - __bfloat162float(a1)));
    ((__nv_bfloat162*)(dl + d))[1] =
        __nv_bfloat162(__float2bfloat16(o1z - __bfloat162float(a2)),
                       __float2bfloat16(o1w - __bfloat162float(a3)));
    ((__nv_bfloat162*)(dl + d + 128))[0] =
        __nv_bfloat162(__float2bfloat16(o2x - __bfloat162float(b0)),
                       __float2bfloat16(o2y - __bfloat162float(b1)));
    ((__nv_bfloat162*)(dl + d + 128))[1] =
        __nv_bfloat162(__float2bfloat16(o2z - __bfloat162float(b2)),
                       __float2bfloat16(o2w - __bfloat162float(b3)));
}

// ---------------------------------------------------------------------------
// V transpose + split from fused QKV (v at col 3072+): -> vt [B*HKV, DH, L]
// ---------------------------------------------------------------------------
__global__ void vtrans_cvt_kernel(const float* __restrict__ qkv,
                                  __nv_bfloat16* __restrict__ vh, __nv_bfloat16* __restrict__ vl)
{
    __shared__ float ts[64][33];
    int z = blockIdx.z;
    const float* src = qkv + (long)(z / HKVc) * Lc * QKVW + 3072 + (z % HKVc) * DHc;
    __nv_bfloat16* dh = vh + (long)z * DHc * Lc;
    __nv_bfloat16* dl = vl + (long)z * DHc * Lc;
    int l0 = blockIdx.y * 64, d0 = blockIdx.x * 32;
    int tx = threadIdx.x, ty = threadIdx.y;
#pragma unroll
    for (int j = 0; j < 8; j++)
        ts[ty + j * 8][tx] = src[(long)(l0 + ty + j * 8) * QKVW + d0 + tx];
    __syncthreads();
#pragma unroll
    for (int j = 0; j < 4; j++) {
        int d  = d0 + ty + j * 8;
        int dy = ty + j * 8;
        float va = ts[tx * 2][dy], vb = ts[tx * 2 + 1][dy];
        __nv_bfloat16 ha = __float2bfloat16(va), hb = __float2bfloat16(vb);
        ((__nv_bfloat162*)&dh[(long)d * Lc + l0])[tx] = __nv_bfloat162(ha, hb);
        ((__nv_bfloat162*)&dl[(long)d * Lc + l0])[tx] =
            __nv_bfloat162(__float2bfloat16(va - __bfloat162float(ha)),
                           __float2bfloat16(vb - __bfloat162float(hb)));
    }
}

// ---------------------------------------------------------------------------
// Register-resident softmax + bf16 hi/lo split (384 threads/row, L=1536)
// ---------------------------------------------------------------------------
__global__ void __launch_bounds__(384, 4) softmax_cvt_kernel(
    const float* __restrict__ S,
    __nv_bfloat16* __restrict__ ph, __nv_bfloat16* __restrict__ pl)
{
    long row = blockIdx.x;
    int  tid = threadIdx.x;
    int  wrp = tid >> 5, ln = tid & 31;
    __shared__ float red[12];

    float4 v = ((const float4*)(S + row * (long)Lc))[tid];

    float mx = fmaxf(fmaxf(v.x, v.y), fmaxf(v.z, v.w));
#pragma unroll
    for (int o = 16; o > 0; o >>= 1)
        mx = fmaxf(mx, __shfl_xor_sync(0xffffffffu, mx, o));
    if (ln == 0) red[wrp] = mx;
    __syncthreads();
    if (tid < 32) {
        float m2 = (tid < 12) ? red[tid] : -INFINITY;
#pragma unroll
        for (int o = 16; o > 0; o >>= 1)
            m2 = fmaxf(m2, __shfl_xor_sync(0xffffffffu, m2, o));
        if (tid == 0) red[0] = m2;
    }
    __syncthreads();
    mx = red[0];
    __syncthreads();

    float e0 = __expf(v.x - mx), e1 = __expf(v.y - mx);
    float e2 = __expf(v.z - mx), e3 = __expf(v.w - mx);

    float sm = (e0 + e1) + (e2 + e3);
#pragma unroll
    for (int o = 16; o > 0; o >>= 1)
        sm += __shfl_xor_sync(0xffffffffu, sm, o);
    if (ln == 0) red[wrp] = sm;
    __syncthreads();
    if (tid < 32) {
        float s2 = (tid < 12) ? red[tid] : 0.f;
#pragma unroll
        for (int o = 16; o > 0; o >>= 1)
            s2 += __shfl_xor_sync(0xffffffffu, s2, o);
        if (tid == 0) red[0] = s2;
    }
    __syncthreads();
    float inv = 1.f / red[0];

    e0 *= inv; e1 *= inv; e2 *= inv; e3 *= inv;
    __nv_bfloat16 h0 = __float2bfloat16(e0), h1 = __float2bfloat16(e1);
    __nv_bfloat16 h2 = __float2bfloat16(e2), h3 = __float2bfloat16(e3);
    long base2 = row * (long)(Lc / 2) + tid * 2;
    ((__nv_bfloat162*)ph)[base2]     = __nv_bfloat162(h0, h1);
    ((__nv_bfloat162*)ph)[base2 + 1] = __nv_bfloat162(h2, h3);
    ((__nv_bfloat162*)pl)[base2] =
        __nv_bfloat162(__float2bfloat16(e0 - __bfloat162float(h0)),
                       __float2bfloat16(e1 - __bfloat162float(h1)));
    ((__nv_bfloat162*)pl)[base2 + 1] =
        __nv_bfloat162(__float2bfloat16(e2 - __bfloat162float(h2)),
                       __float2bfloat16(e3 - __bfloat162float(h3)));
}

// ---------------------------------------------------------------------------
// Host side
// ---------------------------------------------------------------------------
static inline GSeg mkseg(const __nv_bfloat16* Ah, const __nv_bfloat16* Al,
                         const __nv_bfloat16* Bh, const __nv_bfloat16* Bl,
                         float* C, const float* D,
                         __nv_bfloat16* Ch, __nv_bfloat16* Cl,
                         int M, int N, int K, int lda, int ldb, int ldc, int ldd,
                         long sAo, long sAi, long sBo, long sBi,
                         long sCo, long sCi, long sDo,
                         int dv, int rep, float alpha, int nz)
{
    GSeg g;
    g.Ah = Ah; g.Al = Al; g.Bh = Bh; g.Bl = Bl;
    g.C = C; g.D = D; g.Ch = Ch; g.Cl = Cl;
    g.M = M; g.N = N; g.K = K;
    g.lda = lda; g.ldb = ldb; g.ldc = ldc; g.ldd = ldd;
    g.sAo = sAo; g.sAi = sAi; g.sBo = sBo; g.sBi = sBi;
    g.sCo = sCo; g.sCi = sCi; g.sDo = sDo;
    g.div_ = dv; g.rep = rep; g.alpha = alpha;
    g.nx = N / 128; g.ny = M / 128;
    (void)nz;
    return g;
}

extern "C" void kernel_launch(void* const* d_in, const int* in_sizes, int n_in,
                              void* d_out, int out_size)
{
    const float* pg   = (const float*)d_in[0];
    const float* ex   = (const float*)d_in[1];
    const float* cosp = (const float*)d_in[2];
    const float* sinp = (const float*)d_in[3];
    const float* mask = (const float*)d_in[4];
    const float* W[8] = { (const float*)d_in[5],  (const float*)d_in[6],
                          (const float*)d_in[7],  (const float*)d_in[8],
                          (const float*)d_in[9],  (const float*)d_in[10],
                          (const float*)d_in[11], (const float*)d_in[12] };
    float* out = (float*)d_out;

    cudaFuncSetAttribute(gemm_one<0>,  cudaFuncAttributeMaxDynamicSharedMemorySize, SMEM_BYTES);
    cudaFuncSetAttribute(gemm_one<1>,  cudaFuncAttributeMaxDynamicSharedMemorySize, SMEM_BYTES);
    cudaFuncSetAttribute(gemm_pair<0>, cudaFuncAttributeMaxDynamicSharedMemorySize, SMEM_BYTES);

    float *qkv, *sc;
    cudaGetSymbolAddress((void**)&qkv, g_qkv);
    cudaGetSymbolAddress((void**)&sc,  g_scores);

#define GETHL(sym, hp, lp) \
    __nv_bfloat16 *hp, *lp; \
    cudaGetSymbolAddress((void**)&hp, sym##_h); \
    cudaGetSymbolAddress((void**)&lp, sym##_l);

    GETHL(g_pg,  pgh,  pgl)   GETHL(g_ex,  exh,  exl)
    GETHL(g_wc0, wc0h, wc0l)  GETHL(g_wc1, wc1h, wc1l)
    GETHL(g_wo0, wo0h, wo0l)  GETHL(g_wo1, wo1h, wo1l)
    GETHL(g_qb,  qh,   ql)    GETHL(g_kb,  kh,   kl)
    GETHL(g_vt,  vth,  vtl)   GETHL(g_p,   pph,  ppl)
    GETHL(g_attb, atth, attl)

    const int HD  = Hc * DHc;     // 2048
    const int KVD = HKVc * DHc;   // 1024

    // --- all input/weight splits in ONE launch ---
    {
        CvtSegs s;
        const float* xs[NSEG] = { pg, ex, W[0], W[1], W[2], W[4], W[5], W[6], W[3], W[7] };
        __nv_bfloat16* hs[NSEG] = {
            pgh, exh,
            wc0h, wc0h + (long)2048 * DPGc, wc0h + (long)3072 * DPGc,
            wc1h, wc1h + (long)2048 * DEXc, wc1h + (long)3072 * DEXc,
            wo0h, wo1h };
        __nv_bfloat16* ls[NSEG] = {
            pgl, exl,
            wc0l, wc0l + (long)2048 * DPGc, wc0l + (long)3072 * DPGc,
            wc1l, wc1l + (long)2048 * DEXc, wc1l + (long)3072 * DEXc,
            wo0l, wo1l };
        long ns[NSEG] = {
            (long)Bc * L1c * DPGc, (long)Bc * L2c * DEXc,
            (long)HD * DPGc, (long)KVD * DPGc, (long)KVD * DPGc,
            (long)HD * DEXc, (long)KVD * DEXc, (long)KVD * DEXc,
            (long)DPGc * HD, (long)DEXc * HD };
        s.start[0] = 0;
        for (int i = 0; i < NSEG; i++) {
            s.x[i] = xs[i]; s.h[i] = hs[i]; s.l[i] = ls[i];
            s.start[i + 1] = s.start[i] + (ns[i] >> 2);
        }
        long tot = s.start[NSEG];
        cvt_multi_kernel<<<(int)((tot + 1023) / 1024), 256>>>(s);
    }

    // --- fused QKV projections: pg + ex segments in ONE flattened launch ---
    {
        GSeg g0 = mkseg(pgh, pgl, wc0h, wc0l, qkv, nullptr, nullptr, nullptr,
                        L1c, QKVW, DPGc, DPGc, DPGc, QKVW, 0,
                        (long)L1c * DPGc, 0, 0, 0, (long)Lc * QKVW, 0, 0,
                        1, 1, 1.0f, Bc);
        GSeg g1 = mkseg(exh, exl, wc1h, wc1l, qkv + (long)L1c * QKVW, nullptr,
                        nullptr, nullptr,
                        L2c, QKVW, DEXc, DEXc, DEXc, QKVW, 0,
                        (long)L2c * DEXc, 0, 0, 0, (long)Lc * QKVW, 0, 0,
                        1, 1, 1.0f, Bc);
        int c0 = g0.nx * g0.ny * Bc;   // 32*8*4 = 1024
        int c1 = g1.nx * g1.ny * Bc;   // 32*4*4 = 512
        gemm_pair<0><<<c0 + c1, 256, SMEM_BYTES>>>(g0, g1, c0);
    }

    // --- fused RoPE + split for q and k ---
    {
        long tp = (long)Bc * Lc * 12 * 32;
        rope_cvt_kernel<<<(int)((tp + 255) / 256), 256>>>(qkv, cosp, sinp,
                                                          qh, ql, kh, kl, tp);
    }

    // --- V transpose + split ---
    {
        dim3 g(DHc / 32, Lc / 64, Bc * HKVc);
        vtrans_cvt_kernel<<<g, dim3(32, 8)>>>(qkv, vth, vtl);
    }

    // --- scores = q @ k^T * SCALE + mask  [B*H batches, GQA rep=2] ---
    {
        GSeg g = mkseg(qh, ql, kh, kl, sc, mask, nullptr, nullptr,
                       Lc, Lc, DHc, HD, KVD, Lc, Lc,
                       (long)Lc * HD, DHc,
                       (long)Lc * KVD, DHc,
                       (long)Hc * Lc * Lc, (long)Lc * Lc,
                       (long)Lc * Lc,
                       Hc, 2, SCALEc, Bc * Hc);
        dim3 grid(Lc / 128, Lc / 128, Bc * Hc);
        gemm_one<0><<<grid, 256, SMEM_BYTES>>>(g);
    }

    // --- softmax + split (register-resident, single pass) ---
    softmax_cvt_kernel<<<Bc * Hc * Lc, 384>>>(sc, pph, ppl);

    // --- att = P @ V^T, writing bf16 hi/lo directly ---
    {
        GSeg g = mkseg(pph, ppl, vth, vtl, nullptr, nullptr, atth, attl,
                       Lc, DHc, Lc, Lc, Lc, HD, 0,
                       (long)Hc * Lc * Lc, (long)Lc * Lc,
                       (long)HKVc * DHc * Lc, (long)DHc * Lc,
                       (long)Lc * HD, DHc, 0,
                       Hc, 2, 1.0f, Bc * Hc);
        dim3 grid(DHc / 128, Lc / 128, Bc * Hc);
        gemm_one<1><<<grid, 256, SMEM_BYTES>>>(g);
    }

    // --- output projections: out0 + out1 segments in ONE flattened launch ---
    {
        GSeg g0 = mkseg(atth, attl, wo0h, wo0l, out, nullptr, nullptr, nullptr,
                        L1c, DPGc, HD, HD, HD, DPGc, 0,
                        (long)Lc * HD, 0, 0, 0,
                        (long)L1c * DPGc, 0, 0,
                        1, 1, 1.0f, Bc);
        GSeg g1 = mkseg(atth + (long)L1c * HD, attl + (long)L1c * HD,
                        wo1h, wo1l, out + (long)Bc * L1c * DPGc, nullptr,
                        nullptr, nullptr,
                        L2c, DEXc, HD, HD, HD, DEXc, 0,
                        (long)Lc * HD, 0, 0, 0,
                        (long)L2c * DEXc, 0, 0,
                        1, 1, 1.0f, Bc);
        int c0 = g0.nx * g0.ny * Bc;   // 18*8*4 = 576
        int c1 = g1.nx * g1.ny * Bc;   // 8*4*4  = 128
        gemm_pair<0><<<c0 + c1, 256, SMEM_BYTES>>>(g0, g1, c0);
    }
}

// round 16
// speedup vs baseline: 1.0157x; 1.0157x over previous
#include <cuda_runtime.h>
#include <cuda_bf16.h>
#include <math.h>
#include <stdint.h>

// Problem constants
#define Bc   4
#define L1c  1024
#define L2c  512
#define Lc   1536
#define DPGc 2304
#define DEXc 1024
#define Hc   8
#define HKVc 4
#define DHc  256
#define SCALEc 0.0625f
#define QKVW 4096              // fused QKV width: 2048 q + 1024 k + 1024 v

// ---------------------------------------------------------------------------
// Scratch (device globals; allocation-free)
// ---------------------------------------------------------------------------
__device__ __align__(128) float g_qkv[(size_t)Bc * Lc * QKVW];       // fused QKV fp32
__device__ __align__(128) float g_scores[(size_t)Bc * Hc * Lc * Lc];

#define DECL_HL(T, name, count) \
    __device__ __align__(128) T name##_h[count]; \
    __device__ __align__(128) T name##_l[count];

DECL_HL(__nv_bfloat16, g_pg,  (size_t)Bc * L1c * DPGc)
DECL_HL(__nv_bfloat16, g_ex,  (size_t)Bc * L2c * DEXc)
DECL_HL(__nv_bfloat16, g_wc0, (size_t)QKVW * DPGc)     // cat(Wq0,Wk0,Wv0)
DECL_HL(__nv_bfloat16, g_wc1, (size_t)QKVW * DEXc)     // cat(Wq1,Wk1,Wv1)
DECL_HL(__nv_bfloat16, g_wo0, (size_t)DPGc * Hc * DHc)
DECL_HL(__nv_bfloat16, g_wo1, (size_t)DEXc * Hc * DHc)
DECL_HL(__nv_bfloat16, g_qb,  (size_t)Bc * Lc * Hc * DHc)
DECL_HL(__nv_bfloat16, g_kb,  (size_t)Bc * Lc * HKVc * DHc)
DECL_HL(__nv_bfloat16, g_vt,  (size_t)Bc * HKVc * DHc * Lc)   // V^T: [B*HKV, DH, L]
DECL_HL(__nv_bfloat16, g_p,   (size_t)Bc * Hc * Lc * Lc)
DECL_HL(__nv_bfloat16, g_attb,(size_t)Bc * Lc * Hc * DHc)

// ---------------------------------------------------------------------------
// PTX helpers (compute_103-safe: cp.async, ldmatrix, mma.sync only)
// ---------------------------------------------------------------------------
__device__ __forceinline__ uint32_t smem_u32(const void* p) {
    uint32_t a;
    asm("{ .reg .u64 t; cvta.to.shared.u64 t, %1; cvt.u32.u64 %0, t; }" : "=r"(a) : "l"(p));
    return a;
}
#define CP_ASYNC16(dst, src) \
    asm volatile("cp.async.cg.shared.global [%0], [%1], 16;" :: "r"(dst), "l"(src) : "memory")
#define CP_COMMIT() asm volatile("cp.async.commit_group;" ::: "memory")

#define LDMX4(r0, r1, r2, r3, addr) \
    asm volatile("ldmatrix.sync.aligned.m8n8.x4.shared.b16 {%0,%1,%2,%3}, [%4];" \
                 : "=r"(r0), "=r"(r1), "=r"(r2), "=r"(r3) : "r"(addr))

#define MMA16816(c, a, b0, b1) \
    asm volatile("mma.sync.aligned.m16n8k16.row.col.f32.bf16.bf16.f32 " \
                 "{%0,%1,%2,%3}, {%4,%5,%6,%7}, {%8,%9}, {%0,%1,%2,%3};" \
                 : "+f"((c)[0]), "+f"((c)[1]), "+f"((c)[2]), "+f"((c)[3]) \
                 : "r"((a)[0]), "r"((a)[1]), "r"((a)[2]), "r"((a)[3]), \
                   "r"(b0), "r"(b1))

// ---------------------------------------------------------------------------
// bf16x2-split GEMM via mma.sync.  C[m,n] = alpha * sum_k A[m,k]*B[n,k] (+ D)
// Tiles 128x128x64, warp tile 64x32 (8 warps as 2m x 4n).
// 3-stage cp.async pipeline (64KB/stage), single __syncthreads per k-tile.
// Explicit ks-level fragment double-buffering. SW128 swizzle, 256 threads.
// 3 compensation passes: Ah*Bh + Ah*Bl + Al*Bh, fp32 accumulate.
// OUTB=0: fp32 C (+optional D add). OUTB=1: bf16 hi/lo split into Ch/Cl.
// Requires: M,N % 128 == 0, K % 64 == 0 (true at every call site).
// ---------------------------------------------------------------------------
#define STAGE_BYTES 65536                    // 4 tiles x 16KB (Ah,Bh,Al,Bl)
#define NSTAGE 3
#define SMEM_BYTES  (NSTAGE * STAGE_BYTES + 1024)

template <int OUTB>
__global__ void __launch_bounds__(256, 1) gemm_mma(
    const __nv_bfloat16* __restrict__ Ahi, const __nv_bfloat16* __restrict__ Alo,
    const __nv_bfloat16* __restrict__ Bhi, const __nv_bfloat16* __restrict__ Blo,
    float* __restrict__ C, const float* __restrict__ D,
    __nv_bfloat16* __restrict__ Ch, __nv_bfloat16* __restrict__ Cl,
    int M, int N, int K, int lda, int ldb, int ldc, int ldd,
    long sAo, long sAi, long sBo, long sBi, long sCo, long sCi, long sDo,
    int div_, int rep, float alpha)
{
    extern __shared__ char smem_raw[];
    uint32_t sb0 = smem_u32(smem_raw);
    uint32_t sb  = (sb0 + 1023) & ~1023u;
    char* smem_al = smem_raw + (sb - sb0);

    int tid = threadIdx.x, wid = tid >> 5, lane = tid & 31;
    int wm = wid & 1, wn = wid >> 1;      // warp grid 2 (m) x 4 (n), 64x32 each

    int z = blockIdx.z, zo = z / div_, zi = z % div_;
    long aoff = (long)zo * sAo + (long)zi * sAi;
    long boff = (long)zo * sBo + (long)(zi / rep) * sBi;
    Ahi += aoff; Alo += aoff; Bhi += boff; Blo += boff;
    long coff = (long)zo * sCo + (long)zi * sCi;
    if (OUTB) { Ch += coff; Cl += coff; }
    else      { C += coff; if (D) D += (long)zo * sDo; }

    int bm = blockIdx.y * 128;
    int bn = blockIdx.x * 128;

    float acc[4][4][4] = {};              // [mi][ni][reg]

    const int KT = K >> 6;

    // ---- stage loader: 4 tiles (Ah,Bh,Al,Bl), 128 rows x 128B, SW128 ----
#define LOAD_STAGE(ktv)                                                        \
    do {                                                                       \
        uint32_t stb_ = sb + ((ktv) % NSTAGE) * STAGE_BYTES;                   \
        int k0_ = (ktv) << 6;                                                  \
        _Pragma("unroll")                                                      \
        for (int tile = 0; tile < 4; tile++) {                                 \
            const __nv_bfloat16* base =                                        \
                (tile == 0) ? Ahi : (tile == 1) ? Bhi : (tile == 2) ? Alo : Blo;\
            int ld = (tile & 1) ? ldb : lda;                                   \
            int rb = (tile & 1) ? bn : bm;                                     \
            _Pragma("unroll")                                                  \
            for (int j = 0; j < 4; j++) {                                      \
                int idx = j * 256 + tid;                                       \
                int row = idx >> 3, c = idx & 7;                               \
                const __nv_bfloat16* src = base + (long)(rb + row) * ld + k0_ + c * 8; \
                uint32_t doff = (uint32_t)(row * 128 + c * 16);                \
                doff ^= (doff >> 3) & 0x70;                                    \
                CP_ASYNC16(stb_ + tile * 16384 + doff, src);                   \
            }                                                                  \
        }                                                                      \
        CP_COMMIT();                                                           \
    } while (0)

    // ---- fragment loader for one k16 step into buffer slot bi ----
    uint32_t ah[2][4][4], al[2][4][4], bh[2][4][2], bl[2][4][2];
#define LOAD_FRAGS(bi, ks_)                                                    \
    do {                                                                       \
        int arow0 = wm * 64 + (lane & 15);                                     \
        int ac    = 2 * (ks_) + (lane >> 4);                                   \
        _Pragma("unroll")                                                      \
        for (int mi = 0; mi < 4; mi++) {                                       \
            int r = arow0 + mi * 16;                                           \
            uint32_t off = (uint32_t)(r * 128 + ((ac ^ (r & 7)) << 4));        \
            LDMX4(ah[bi][mi][0], ah[bi][mi][1], ah[bi][mi][2], ah[bi][mi][3],  \
                  stb + off);                                                  \
            LDMX4(al[bi][mi][0], al[bi][mi][1], al[bi][mi][2], al[bi][mi][3],  \
                  stb + 32768 + off);                                          \
        }                                                                      \
        int bn0 = wn * 32 + ((lane >> 4) << 3) + (lane & 7);                   \
        int bcc = 2 * (ks_) + ((lane >> 3) & 1);                               \
        _Pragma("unroll")                                                      \
        for (int nj = 0; nj < 2; nj++) {                                       \
            int r = bn0 + nj * 16;                                             \
            uint32_t off = (uint32_t)(r * 128 + ((bcc ^ (r & 7)) << 4));       \
            uint32_t t0, t1, t2, t3;                                           \
            LDMX4(t0, t1, t2, t3, stb + 16384 + off);                          \
            bh[bi][2 * nj][0] = t0;     bh[bi][2 * nj][1] = t1;                \
            bh[bi][2 * nj + 1][0] = t2; bh[bi][2 * nj + 1][1] = t3;            \
            LDMX4(t0, t1, t2, t3, stb + 49152 + off);                          \
            bl[bi][2 * nj][0] = t0;     bl[bi][2 * nj][1] = t1;                \
            bl[bi][2 * nj + 1][0] = t2; bl[bi][2 * nj + 1][1] = t3;            \
        }                                                                      \
    } while (0)

    LOAD_STAGE(0);
    if (KT > 1) LOAD_STAGE(1);

    for (int kt = 0; kt < KT; kt++) {
        if (kt + 1 < KT) {
            asm volatile("cp.async.wait_group 1;" ::: "memory");
        } else {
            asm volatile("cp.async.wait_group 0;" ::: "memory");
        }
        __syncthreads();
        if (kt + 2 < KT) LOAD_STAGE(kt + 2);

        uint32_t stb = sb + (kt % NSTAGE) * STAGE_BYTES;

        LOAD_FRAGS(0, 0);
#pragma unroll
        for (int ks = 0; ks < 4; ks++) {
            int cur = ks & 1;
            if (ks < 3) LOAD_FRAGS((ks + 1) & 1, ks + 1);
#pragma unroll
            for (int mi = 0; mi < 4; mi++)
#pragma unroll
                for (int ni = 0; ni < 4; ni++) {
                    MMA16816(acc[mi][ni], ah[cur][mi], bh[cur][ni][0], bh[cur][ni][1]);
                    MMA16816(acc[mi][ni], ah[cur][mi], bl[cur][ni][0], bl[cur][ni][1]);
                    MMA16816(acc[mi][ni], al[cur][mi], bh[cur][ni][0], bh[cur][ni][1]);
                }
        }
    }
    __syncthreads();   // all warps done with last stage before Ct overwrites smem

    // ---- epilogue: regs -> SMEM (stride 132) -> coalesced GMEM ----
    float* Ct = (float*)smem_al;
    int tq = lane >> 2, tr2 = (lane & 3) * 2;
#pragma unroll
    for (int mi = 0; mi < 4; mi++)
#pragma unroll
        for (int ni = 0; ni < 4; ni++) {
            int r0 = wm * 64 + mi * 16 + tq;
            int cc = wn * 32 + ni * 8 + tr2;
            *(float2*)&Ct[r0 * 132 + cc] =
                make_float2(acc[mi][ni][0] * alpha, acc[mi][ni][1] * alpha);
            *(float2*)&Ct[(r0 + 8) * 132 + cc] =
                make_float2(acc[mi][ni][2] * alpha, acc[mi][ni][3] * alpha);
        }
    __syncthreads();

#pragma unroll
    for (int it = 0; it < 16; it++) {
        int r = it * 8 + wid;
        float4 v = *(float4*)&Ct[r * 132 + lane * 4];
        if (OUTB) {
            __nv_bfloat16 h0 = __float2bfloat16(v.x), h1 = __float2bfloat16(v.y);
            __nv_bfloat16 h2 = __float2bfloat16(v.z), h3 = __float2bfloat16(v.w);
            long base = (long)(bm + r) * ldc + bn + lane * 4;
            ((__nv_bfloat162*)(Ch + base))[0] = __nv_bfloat162(h0, h1);
            ((__nv_bfloat162*)(Ch + base))[1] = __nv_bfloat162(h2, h3);
            ((__nv_bfloat162*)(Cl + base))[0] =
                __nv_bfloat162(__float2bfloat16(v.x - __bfloat162float(h0)),
                               __float2bfloat16(v.y - __bfloat162float(h1)));
            ((__nv_bfloat162*)(Cl + base))[1] =
                __nv_bfloat162(__float2bfloat16(v.z - __bfloat162float(h2)),
                               __float2bfloat16(v.w - __bfloat162float(h3)));
        } else {
            if (D) {
                const float* dp = &D[(long)(bm + r) * ldd + bn + lane * 4];
                v.x += dp[0]; v.y += dp[1]; v.z += dp[2]; v.w += dp[3];
            }
            *(float4*)&C[(long)(bm + r) * ldc + bn + lane * 4] = v;
        }
    }
}

// ---------------------------------------------------------------------------
// Multi-segment fp32 -> bf16 hi/lo split, MLP=4 per thread (one launch)
// ---------------------------------------------------------------------------
#define NSEG 10
struct CvtSegs {
    const float* x[NSEG];
    __nv_bfloat16* h[NSEG];
    __nv_bfloat16* l[NSEG];
    long start[NSEG + 1];     // prefix sums in float4 units
};

__global__ void cvt_multi_kernel(CvtSegs s)
{
    long base = (long)blockIdx.x * 1024 + threadIdx.x;
#pragma unroll
    for (int u = 0; u < 4; u++) {
        long i = base + u * 256;
        if (i >= s.start[NSEG]) return;
        int seg = 0;
#pragma unroll
        for (int j = 1; j < NSEG; j++) seg += (i >= s.start[j]);
        long off = i - s.start[seg];

        float4 v = ((const float4*)s.x[seg])[off];
        __nv_bfloat16 h0 = __float2bfloat16(v.x), h1 = __float2bfloat16(v.y);
        __nv_bfloat16 h2 = __float2bfloat16(v.z), h3 = __float2bfloat16(v.w);
        ((__nv_bfloat162*)s.h[seg])[off * 2 + 0] = __nv_bfloat162(h0, h1);
        ((__nv_bfloat162*)s.h[seg])[off * 2 + 1] = __nv_bfloat162(h2, h3);
        ((__nv_bfloat162*)s.l[seg])[off * 2 + 0] =
            __nv_bfloat162(__float2bfloat16(v.x - __bfloat162float(h0)),
                           __float2bfloat16(v.y - __bfloat162float(h1)));
        ((__nv_bfloat162*)s.l[seg])[off * 2 + 1] =
            __nv_bfloat162(__float2bfloat16(v.z - __bfloat162float(h2)),
                           __float2bfloat16(v.w - __bfloat162float(h3)));
    }
}

// ---------------------------------------------------------------------------
// Fused prep: RoPE+split (q,k) AND V-transpose+split, one launch.
// Blocks [0, ROPE_BLKS): RoPE.  Blocks [ROPE_BLKS, ROPE_BLKS+VT_BLKS): vtrans.
// ---------------------------------------------------------------------------
#define ROPE_BLKS 9216      // (B*Lc*12*32) / 256
#define VT_BLKS   3072      // (DHc/32) * (Lc/64) * (B*HKVc) = 8*24*16

__global__ void prep_kernel(const float* __restrict__ qkv,
                            const float* __restrict__ cosp, const float* __restrict__ sinp,
                            __nv_bfloat16* __restrict__ qh, __nv_bfloat16* __restrict__ ql,
                            __nv_bfloat16* __restrict__ kh, __nv_bfloat16* __restrict__ kl,
                            __nv_bfloat16* __restrict__ vh, __nv_bfloat16* __restrict__ vl)
{
    __shared__ float ts[64][33];
    int blk = blockIdx.x;
    int tid = threadIdx.x;

    if (blk < ROPE_BLKS) {
        // ---------------- RoPE + split (vectorized x4) ----------------
        long idx = (long)blk * 256 + tid;
        int  d   = (int)(idx & 31) * 4;
        long t   = idx >> 5;
        int  h12 = (int)(t % 12);
        long bl  = t / 12;

        float4 c4 = *(const float4*)&cosp[bl * 128 + d];
        float4 s4 = *(const float4*)&sinp[bl * 128 + d];

        const float* row = qkv + bl * QKVW;
        __nv_bfloat16 *dh, *dl;
        int colbase;
        if (h12 < 8) {
            colbase = h12 * DHc;
            long dbase = bl * (Hc * DHc) + h12 * DHc;
            dh = qh + dbase; dl = ql + dbase;
        } else {
            colbase = 2048 + (h12 - 8) * DHc;
            long dbase = bl * (HKVc * DHc) + (h12 - 8) * DHc;
            dh = kh + dbase; dl = kl + dbase;
        }
        float4 x1 = *(const float4*)&row[colbase + d];
        float4 x2 = *(const float4*)&row[colbase + d + 128];

        float o1x = x1.x * c4.x - x2.x * s4.x,  o2x = x2.x * c4.x + x1.x * s4.x;
        float o1y = x1.y * c4.y - x2.y * s4.y,  o2y = x2.y * c4.y + x1.y * s4.y;
        float o1z = x1.z * c4.z - x2.z * s4.z,  o2z = x2.z * c4.z + x1.z * s4.z;
        float o1w = x1.w * c4.w - x2.w * s4.w,  o2w = x2.w * c4.w + x1.w * s4.w;

        __nv_bfloat16 a0 = __float2bfloat16(o1x), a1 = __float2bfloat16(o1y);
        __nv_bfloat16 a2 = __float2bfloat16(o1z), a3 = __float2bfloat16(o1w);
        __nv_bfloat16 b0 = __float2bfloat16(o2x), b1 = __float2bfloat16(o2y);
        __nv_bfloat16 b2 = __float2bfloat16(o2z), b3 = __float2bfloat16(o2w);

        ((__nv_bfloat162*)(dh + d))[0]       = __nv_bfloat162(a0, a1);
        ((__nv_bfloat162*)(dh + d))[1]       = __nv_bfloat162(a2, a3);
        ((__nv_bfloat162*)(dh + d + 128))[0] = __nv_bfloat162(b0, b1);
        ((__nv_bfloat162*)(dh + d + 128))[1] = __nv_bfloat162(b2, b3);

        ((__nv_bfloat162*)(dl + d))[0] =
            __nv_bfloat162(__float2bfloat16(o1x - __bfloat162float(a0)),
                           __float2bfloat16(o1y - __bfloat162float(a1)));
        ((__nv_bfloat162*)(dl + d))[1] =
            __nv_bfloat162(__float2bfloat16(o1z - __bfloat162float(a2)),
                           __float2bfloat16(o1w - __bfloat162float(a3)));
        ((__nv_bfloat162*)(dl + d + 128))[0] =
            __nv_bfloat162(__float2bfloat16(o2x - __bfloat162float(b0)),
                           __float2bfloat16(o2y - __bfloat162float(b1)));
        ((__nv_bfloat162*)(dl + d + 128))[1] =
            __nv_bfloat162(__float2bfloat16(o2z - __bfloat162float(b2)),
                           __float2bfloat16(o2w - __bfloat162float(b3)));
    } else {
        // ---------------- V transpose + split ----------------
        int f = blk - ROPE_BLKS;
        int bx = f & 7;              // DHc/32 = 8
        int rem = f >> 3;
        int by = rem % 24;           // Lc/64 = 24
        int z  = rem / 24;           // B*HKV = 16

        const float* src = qkv + (long)(z / HKVc) * Lc * QKVW + 3072 + (z % HKVc) * DHc;
        __nv_bfloat16* dh = vh + (long)z * DHc * Lc;
        __nv_bfloat16* dl = vl + (long)z * DHc * Lc;
        int l0 = by * 64, d0 = bx * 32;
        int tx = tid & 31, ty = tid >> 5;   // (32, 8)
#pragma unroll
        for (int j = 0; j < 8; j++)
            ts[ty + j * 8][tx] = src[(long)(l0 + ty + j * 8) * QKVW + d0 + tx];
        __syncthreads();
#pragma unroll
        for (int j = 0; j < 4; j++) {
            int d  = d0 + ty + j * 8;
            int dy = ty + j * 8;
            float va = ts[tx * 2][dy], vb = ts[tx * 2 + 1][dy];
            __nv_bfloat16 ha = __float2bfloat16(va), hb = __float2bfloat16(vb);
            ((__nv_bfloat162*)&dh[(long)d * Lc + l0])[tx] = __nv_bfloat162(ha, hb);
            ((__nv_bfloat162*)&dl[(long)d * Lc + l0])[tx] =
                __nv_bfloat162(__float2bfloat16(va - __bfloat162float(ha)),
                               __float2bfloat16(vb - __bfloat162float(hb)));
        }
    }
}

// ---------------------------------------------------------------------------
// Register-resident softmax + bf16 hi/lo split (384 threads/row, L=1536)
// ---------------------------------------------------------------------------
__global__ void __launch_bounds__(384, 4) softmax_cvt_kernel(
    const float* __restrict__ S,
    __nv_bfloat16* __restrict__ ph, __nv_bfloat16* __restrict__ pl)
{
    long row = blockIdx.x;
    int  tid = threadIdx.x;
    int  wrp = tid >> 5, ln = tid & 31;
    __shared__ float red[12];

    float4 v = ((const float4*)(S + row * (long)Lc))[tid];

    float mx = fmaxf(fmaxf(v.x, v.y), fmaxf(v.z, v.w));
#pragma unroll
    for (int o = 16; o > 0; o >>= 1)
        mx = fmaxf(mx, __shfl_xor_sync(0xffffffffu, mx, o));
    if (ln == 0) red[wrp] = mx;
    __syncthreads();
    if (tid < 32) {
        float m2 = (tid < 12) ? red[tid] : -INFINITY;
#pragma unroll
        for (int o = 16; o > 0; o >>= 1)
            m2 = fmaxf(m2, __shfl_xor_sync(0xffffffffu, m2, o));
        if (tid == 0) red[0] = m2;
    }
    __syncthreads();
    mx = red[0];
    __syncthreads();

    float e0 = __expf(v.x - mx), e1 = __expf(v.y - mx);
    float e2 = __expf(v.z - mx), e3 = __expf(v.w - mx);

    float sm = (e0 + e1) + (e2 + e3);
#pragma unroll
    for (int o = 16; o > 0; o >>= 1)
        sm += __shfl_xor_sync(0xffffffffu, sm, o);
    if (ln == 0) red[wrp] = sm;
    __syncthreads();
    if (tid < 32) {
        float s2 = (tid < 12) ? red[tid] : 0.f;
#pragma unroll
        for (int o = 16; o > 0; o >>= 1)
            s2 += __shfl_xor_sync(0xffffffffu, s2, o);
        if (tid == 0) red[0] = s2;
    }
    __syncthreads();
    float inv = 1.f / red[0];

    e0 *= inv; e1 *= inv; e2 *= inv; e3 *= inv;
    __nv_bfloat16 h0 = __float2bfloat16(e0), h1 = __float2bfloat16(e1);
    __nv_bfloat16 h2 = __float2bfloat16(e2), h3 = __float2bfloat16(e3);
    long base2 = row * (long)(Lc / 2) + tid * 2;
    ((__nv_bfloat162*)ph)[base2]     = __nv_bfloat162(h0, h1);
    ((__nv_bfloat162*)ph)[base2 + 1] = __nv_bfloat162(h2, h3);
    ((__nv_bfloat162*)pl)[base2] =
        __nv_bfloat162(__float2bfloat16(e0 - __bfloat162float(h0)),
                       __float2bfloat16(e1 - __bfloat162float(h1)));
    ((__nv_bfloat162*)pl)[base2 + 1] =
        __nv_bfloat162(__float2bfloat16(e2 - __bfloat162float(h2)),
                       __float2bfloat16(e3 - __bfloat162float(h3)));
}

// ---------------------------------------------------------------------------
// Host side
// ---------------------------------------------------------------------------
static inline void run_gemm(const __nv_bfloat16* Ah, const __nv_bfloat16* Al,
                            const __nv_bfloat16* Bh, const __nv_bfloat16* Bl,
                            float* C, const float* D,
                            int M, int N, int K, int lda, int ldb, int ldc, int ldd,
                            long sAo, long sAi, long sBo, long sBi,
                            long sCo, long sCi, long sDo,
                            int nb, int dv, int rep, float alpha)
{
    dim3 grid(N / 128, M / 128, nb);
    gemm_mma<0><<<grid, 256, SMEM_BYTES>>>(Ah, Al, Bh, Bl, C, D, nullptr, nullptr,
                                           M, N, K, lda, ldb, ldc, ldd,
                                           sAo, sAi, sBo, sBi, sCo, sCi, sDo,
                                           dv, rep, alpha);
}

static inline void run_gemm_b16(const __nv_bfloat16* Ah, const __nv_bfloat16* Al,
                                const __nv_bfloat16* Bh, const __nv_bfloat16* Bl,
                                __nv_bfloat16* Ch, __nv_bfloat16* Cl,
                                int M, int N, int K, int lda, int ldb, int ldc,
                                long sAo, long sAi, long sBo, long sBi,
                                long sCo, long sCi,
                                int nb, int dv, int rep, float alpha)
{
    dim3 grid(N / 128, M / 128, nb);
    gemm_mma<1><<<grid, 256, SMEM_BYTES>>>(Ah, Al, Bh, Bl, nullptr, nullptr, Ch, Cl,
                                           M, N, K, lda, ldb, ldc, 0,
                                           sAo, sAi, sBo, sBi, sCo, sCi, 0,
                                           dv, rep, alpha);
}

extern "C" void kernel_launch(void* const* d_in, const int* in_sizes, int n_in,
                              void* d_out, int out_size)
{
    const float* pg   = (const float*)d_in[0];
    const float* ex   = (const float*)d_in[1];
    const float* cosp = (const float*)d_in[2];
    const float* sinp = (const float*)d_in[3];
    const float* mask = (const float*)d_in[4];
    const float* W[8] = { (const float*)d_in[5],  (const float*)d_in[6],
                          (const float*)d_in[7],  (const float*)d_in[8],
                          (const float*)d_in[9],  (const float*)d_in[10],
                          (const float*)d_in[11], (const float*)d_in[12] };
    float* out = (float*)d_out;

    cudaFuncSetAttribute(gemm_mma<0>, cudaFuncAttributeMaxDynamicSharedMemorySize, SMEM_BYTES);
    cudaFuncSetAttribute(gemm_mma<1>, cudaFuncAttributeMaxDynamicSharedMemorySize, SMEM_BYTES);

    float *qkv, *sc;
    cudaGetSymbolAddress((void**)&qkv, g_qkv);
    cudaGetSymbolAddress((void**)&sc,  g_scores);

#define GETHL(sym, hp, lp) \
    __nv_bfloat16 *hp, *lp; \
    cudaGetSymbolAddress((void**)&hp, sym##_h); \
    cudaGetSymbolAddress((void**)&lp, sym##_l);

    GETHL(g_pg,  pgh,  pgl)   GETHL(g_ex,  exh,  exl)
    GETHL(g_wc0, wc0h, wc0l)  GETHL(g_wc1, wc1h, wc1l)
    GETHL(g_wo0, wo0h, wo0l)  GETHL(g_wo1, wo1h, wo1l)
    GETHL(g_qb,  qh,   ql)    GETHL(g_kb,  kh,   kl)
    GETHL(g_vt,  vth,  vtl)   GETHL(g_p,   pph,  ppl)
    GETHL(g_attb, atth, attl)

    const int HD  = Hc * DHc;     // 2048
    const int KVD = HKVc * DHc;   // 1024

    // --- all input/weight splits in ONE launch (MLP=4 per thread) ---
    {
        CvtSegs s;
        const float* xs[NSEG] = { pg, ex, W[0], W[1], W[2], W[4], W[5], W[6], W[3], W[7] };
        __nv_bfloat16* hs[NSEG] = {
            pgh, exh,
            wc0h, wc0h + (long)2048 * DPGc, wc0h + (long)3072 * DPGc,
            wc1h, wc1h + (long)2048 * DEXc, wc1h + (long)3072 * DEXc,
            wo0h, wo1h };
        __nv_bfloat16* ls[NSEG] = {
            pgl, exl,
            wc0l, wc0l + (long)2048 * DPGc, wc0l + (long)3072 * DPGc,
            wc1l, wc1l + (long)2048 * DEXc, wc1l + (long)3072 * DEXc,
            wo0l, wo1l };
        long ns[NSEG] = {
            (long)Bc * L1c * DPGc, (long)Bc * L2c * DEXc,
            (long)HD * DPGc, (long)KVD * DPGc, (long)KVD * DPGc,
            (long)HD * DEXc, (long)KVD * DEXc, (long)KVD * DEXc,
            (long)DPGc * HD, (long)DEXc * HD };
        s.start[0] = 0;
        for (int i = 0; i < NSEG; i++) {
            s.x[i] = xs[i]; s.h[i] = hs[i]; s.l[i] = ls[i];
            s.start[i + 1] = s.start[i] + (ns[i] >> 2);
        }
        long tot = s.start[NSEG];
        cvt_multi_kernel<<<(int)((tot + 1023) / 1024), 256>>>(s);
    }

    // --- fused QKV projections (2 launches, dim3 grids) ---
    run_gemm(pgh, pgl, wc0h, wc0l, qkv, nullptr, L1c, QKVW, DPGc,
             DPGc, DPGc, QKVW, 0,
             (long)L1c * DPGc, 0, 0, 0, (long)Lc * QKVW, 0, 0, Bc, 1, 1, 1.0f);
    run_gemm(exh, exl, wc1h, wc1l, qkv + (long)L1c * QKVW, nullptr, L2c, QKVW, DEXc,
             DEXc, DEXc, QKVW, 0,
             (long)L2c * DEXc, 0, 0, 0, (long)Lc * QKVW, 0, 0, Bc, 1, 1, 1.0f);

    // --- fused RoPE(q,k) + V-transpose in ONE launch ---
    prep_kernel<<<ROPE_BLKS + VT_BLKS, 256>>>(qkv, cosp, sinp,
                                              qh, ql, kh, kl, vth, vtl);

    // --- scores = q @ k^T * SCALE + mask  [B*H batches, GQA rep=2] ---
    run_gemm(qh, ql, kh, kl, sc, mask, Lc, Lc, DHc,
             HD, KVD, Lc, Lc,
             (long)Lc * HD, DHc,
             (long)Lc * KVD, DHc,
             (long)Hc * Lc * Lc, (long)Lc * Lc,
             (long)Lc * Lc,
             Bc * Hc, Hc, 2, SCALEc);

    // --- softmax + split (register-resident, single pass) ---
    softmax_cvt_kernel<<<Bc * Hc * Lc, 384>>>(sc, pph, ppl);

    // --- att = P @ V^T, writing bf16 hi/lo directly (fused epilogue) ---
    run_gemm_b16(pph, ppl, vth, vtl, atth, attl, Lc, DHc, Lc,
                 Lc, Lc, HD,
                 (long)Hc * Lc * Lc, (long)Lc * Lc,
                 (long)HKVc * DHc * Lc, (long)DHc * Lc,
                 (long)Lc * HD, DHc,
                 Bc * Hc, Hc, 2, 1.0f);

    // --- output projections ---
    run_gemm(atth, attl, wo0h, wo0l, out, nullptr, L1c, DPGc, HD,
             HD, HD, DPGc, 0,
             (long)Lc * HD, 0, 0, 0,
             (long)L1c * DPGc, 0, 0, Bc, 1, 1, 1.0f);
    run_gemm(atth + (long)L1c * HD, attl + (long)L1c * HD, wo1h, wo1l,
             out + (long)Bc * L1c * DPGc, nullptr, L2c, DEXc, HD,
             HD, HD, DEXc, 0,
             (long)Lc * HD, 0, 0, 0,
             (long)L2c * DEXc, 0, 0, Bc, 1, 1, 1.0f);
}

// round 17
// speedup vs baseline: 1.0250x; 1.0091x over previous
#include <cuda_runtime.h>
#include <cuda_bf16.h>
#include <math.h>
#include <stdint.h>

// Problem constants
#define Bc   4
#define L1c  1024
#define L2c  512
#define Lc   1536
#define DPGc 2304
#define DEXc 1024
#define Hc   8
#define HKVc 4
#define DHc  256
#define SCALEc 0.0625f
#define QKVW 4096              // fused QKV width: 2048 q + 1024 k + 1024 v

// ---------------------------------------------------------------------------
// Scratch (device globals; allocation-free)
// ---------------------------------------------------------------------------
__device__ __align__(128) float g_qkv[(size_t)Bc * Lc * QKVW];       // fused QKV fp32
__device__ __align__(128) float g_scores[(size_t)Bc * Hc * Lc * Lc];

#define DECL_HL(T, name, count) \
    __device__ __align__(128) T name##_h[count]; \
    __device__ __align__(128) T name##_l[count];

DECL_HL(__nv_bfloat16, g_pg,  (size_t)Bc * L1c * DPGc)
DECL_HL(__nv_bfloat16, g_ex,  (size_t)Bc * L2c * DEXc)
DECL_HL(__nv_bfloat16, g_wc0, (size_t)QKVW * DPGc)     // cat(Wq0,Wk0,Wv0)
DECL_HL(__nv_bfloat16, g_wc1, (size_t)QKVW * DEXc)     // cat(Wq1,Wk1,Wv1)
DECL_HL(__nv_bfloat16, g_wo0, (size_t)DPGc * Hc * DHc)
DECL_HL(__nv_bfloat16, g_wo1, (size_t)DEXc * Hc * DHc)
DECL_HL(__nv_bfloat16, g_qb,  (size_t)Bc * Lc * Hc * DHc)
DECL_HL(__nv_bfloat16, g_kb,  (size_t)Bc * Lc * HKVc * DHc)
DECL_HL(__nv_bfloat16, g_vt,  (size_t)Bc * HKVc * DHc * Lc)   // V^T: [B*HKV, DH, L]
DECL_HL(__nv_bfloat16, g_p,   (size_t)Bc * Hc * Lc * Lc)
DECL_HL(__nv_bfloat16, g_attb,(size_t)Bc * Lc * Hc * DHc)

// ---------------------------------------------------------------------------
// PTX helpers (compute_103-safe: cp.async, ldmatrix, mma.sync only)
// ---------------------------------------------------------------------------
__device__ __forceinline__ uint32_t smem_u32(const void* p) {
    uint32_t a;
    asm("{ .reg .u64 t; cvta.to.shared.u64 t, %1; cvt.u32.u64 %0, t; }" : "=r"(a) : "l"(p));
    return a;
}
#define CP_ASYNC16(dst, src) \
    asm volatile("cp.async.cg.shared.global [%0], [%1], 16;" :: "r"(dst), "l"(src) : "memory")
#define CP_COMMIT() asm volatile("cp.async.commit_group;" ::: "memory")

#define LDMX4(r0, r1, r2, r3, addr) \
    asm volatile("ldmatrix.sync.aligned.m8n8.x4.shared.b16 {%0,%1,%2,%3}, [%4];" \
                 : "=r"(r0), "=r"(r1), "=r"(r2), "=r"(r3) : "r"(addr))

#define MMA16816(c, a, b0, b1) \
    asm volatile("mma.sync.aligned.m16n8k16.row.col.f32.bf16.bf16.f32 " \
                 "{%0,%1,%2,%3}, {%4,%5,%6,%7}, {%8,%9}, {%0,%1,%2,%3};" \
                 : "+f"((c)[0]), "+f"((c)[1]), "+f"((c)[2]), "+f"((c)[3]) \
                 : "r"((a)[0]), "r"((a)[1]), "r"((a)[2]), "r"((a)[3]), \
                   "r"(b0), "r"(b1))

// ---------------------------------------------------------------------------
// bf16x2-split GEMM via mma.sync.  C[m,n] = alpha * sum_k A[m,k]*B[n,k] (+ D)
// Tiles 128x128x64, warp tile 64x32 (8 warps as 2m x 4n).
// 3-stage cp.async pipeline (64KB/stage), single __syncthreads per k-tile.
// Explicit ks-level fragment double-buffering. SW128 swizzle, 256 threads.
// 3 compensation passes: Ah*Bh + Ah*Bl + Al*Bh, fp32 accumulate.
// OUTB=0: fp32 C (+optional vectorized D add). OUTB=1: bf16 hi/lo into Ch/Cl.
// Requires: M,N % 128 == 0, K % 64 == 0, ldd % 4 == 0 (true at call sites).
// ---------------------------------------------------------------------------
#define STAGE_BYTES 65536                    // 4 tiles x 16KB (Ah,Bh,Al,Bl)
#define NSTAGE 3
#define SMEM_BYTES  (NSTAGE * STAGE_BYTES + 1024)

template <int OUTB>
__global__ void __launch_bounds__(256, 1) gemm_mma(
    const __nv_bfloat16* __restrict__ Ahi, const __nv_bfloat16* __restrict__ Alo,
    const __nv_bfloat16* __restrict__ Bhi, const __nv_bfloat16* __restrict__ Blo,
    float* __restrict__ C, const float* __restrict__ D,
    __nv_bfloat16* __restrict__ Ch, __nv_bfloat16* __restrict__ Cl,
    int M, int N, int K, int lda, int ldb, int ldc, int ldd,
    long sAo, long sAi, long sBo, long sBi, long sCo, long sCi, long sDo,
    int div_, int rep, float alpha)
{
    extern __shared__ char smem_raw[];
    uint32_t sb0 = smem_u32(smem_raw);
    uint32_t sb  = (sb0 + 1023) & ~1023u;
    char* smem_al = smem_raw + (sb - sb0);

    int tid = threadIdx.x, wid = tid >> 5, lane = tid & 31;
    int wm = wid & 1, wn = wid >> 1;      // warp grid 2 (m) x 4 (n), 64x32 each

    int z = blockIdx.z, zo = z / div_, zi = z % div_;
    long aoff = (long)zo * sAo + (long)zi * sAi;
    long boff = (long)zo * sBo + (long)(zi / rep) * sBi;
    Ahi += aoff; Alo += aoff; Bhi += boff; Blo += boff;
    long coff = (long)zo * sCo + (long)zi * sCi;
    if (OUTB) { Ch += coff; Cl += coff; }
    else      { C += coff; if (D) D += (long)zo * sDo; }

    int bm = blockIdx.y * 128;
    int bn = blockIdx.x * 128;

    float acc[4][4][4] = {};              // [mi][ni][reg]

    const int KT = K >> 6;

    // ---- stage loader: 4 tiles (Ah,Bh,Al,Bl), 128 rows x 128B, SW128 ----
#define LOAD_STAGE(ktv)                                                        \
    do {                                                                       \
        uint32_t stb_ = sb + ((ktv) % NSTAGE) * STAGE_BYTES;                   \
        int k0_ = (ktv) << 6;                                                  \
        _Pragma("unroll")                                                      \
        for (int tile = 0; tile < 4; tile++) {                                 \
            const __nv_bfloat16* base =                                        \
                (tile == 0) ? Ahi : (tile == 1) ? Bhi : (tile == 2) ? Alo : Blo;\
            int ld = (tile & 1) ? ldb : lda;                                   \
            int rb = (tile & 1) ? bn : bm;                                     \
            _Pragma("unroll")                                                  \
            for (int j = 0; j < 4; j++) {                                      \
                int idx = j * 256 + tid;                                       \
                int row = idx >> 3, c = idx & 7;                               \
                const __nv_bfloat16* src = base + (long)(rb + row) * ld + k0_ + c * 8; \
                uint32_t doff = (uint32_t)(row * 128 + c * 16);                \
                doff ^= (doff >> 3) & 0x70;                                    \
                CP_ASYNC16(stb_ + tile * 16384 + doff, src);                   \
            }                                                                  \
        }                                                                      \
        CP_COMMIT();                                                           \
    } while (0)

    // ---- fragment loader for one k16 step into buffer slot bi ----
    uint32_t ah[2][4][4], al[2][4][4], bh[2][4][2], bl[2][4][2];
#define LOAD_FRAGS(bi, ks_)                                                    \
    do {                                                                       \
        int arow0 = wm * 64 + (lane & 15);                                     \
        int ac    = 2 * (ks_) + (lane >> 4);                                   \
        _Pragma("unroll")                                                      \
        for (int mi = 0; mi < 4; mi++) {                                       \
            int r = arow0 + mi * 16;                                           \
            uint32_t off = (uint32_t)(r * 128 + ((ac ^ (r & 7)) << 4));        \
            LDMX4(ah[bi][mi][0], ah[bi][mi][1], ah[bi][mi][2], ah[bi][mi][3],  \
                  stb + off);                                                  \
            LDMX4(al[bi][mi][0], al[bi][mi][1], al[bi][mi][2], al[bi][mi][3],  \
                  stb + 32768 + off);                                          \
        }                                                                      \
        int bn0 = wn * 32 + ((lane >> 4) << 3) + (lane & 7);                   \
        int bcc = 2 * (ks_) + ((lane >> 3) & 1);                               \
        _Pragma("unroll")                                                      \
        for (int nj = 0; nj < 2; nj++) {                                       \
            int r = bn0 + nj * 16;                                             \
            uint32_t off = (uint32_t)(r * 128 + ((bcc ^ (r & 7)) << 4));       \
            uint32_t t0, t1, t2, t3;                                           \
            LDMX4(t0, t1, t2, t3, stb + 16384 + off);                          \
            bh[bi][2 * nj][0] = t0;     bh[bi][2 * nj][1] = t1;                \
            bh[bi][2 * nj + 1][0] = t2; bh[bi][2 * nj + 1][1] = t3;            \
            LDMX4(t0, t1, t2, t3, stb + 49152 + off);                          \
            bl[bi][2 * nj][0] = t0;     bl[bi][2 * nj][1] = t1;                \
            bl[bi][2 * nj + 1][0] = t2; bl[bi][2 * nj + 1][1] = t3;            \
        }                                                                      \
    } while (0)

    LOAD_STAGE(0);
    if (KT > 1) LOAD_STAGE(1);

    for (int kt = 0; kt < KT; kt++) {
        if (kt + 1 < KT) {
            asm volatile("cp.async.wait_group 1;" ::: "memory");
        } else {
            asm volatile("cp.async.wait_group 0;" ::: "memory");
        }
        __syncthreads();
        if (kt + 2 < KT) LOAD_STAGE(kt + 2);

        uint32_t stb = sb + (kt % NSTAGE) * STAGE_BYTES;

        LOAD_FRAGS(0, 0);
#pragma unroll
        for (int ks = 0; ks < 4; ks++) {
            int cur = ks & 1;
            if (ks < 3) LOAD_FRAGS((ks + 1) & 1, ks + 1);
#pragma unroll
            for (int mi = 0; mi < 4; mi++)
#pragma unroll
                for (int ni = 0; ni < 4; ni++) {
                    MMA16816(acc[mi][ni], ah[cur][mi], bh[cur][ni][0], bh[cur][ni][1]);
                    MMA16816(acc[mi][ni], ah[cur][mi], bl[cur][ni][0], bl[cur][ni][1]);
                    MMA16816(acc[mi][ni], al[cur][mi], bh[cur][ni][0], bh[cur][ni][1]);
                }
        }
    }
    __syncthreads();   // all warps done with last stage before Ct overwrites smem

    // ---- epilogue: regs -> SMEM (stride 132) -> coalesced GMEM ----
    float* Ct = (float*)smem_al;
    int tq = lane >> 2, tr2 = (lane & 3) * 2;
#pragma unroll
    for (int mi = 0; mi < 4; mi++)
#pragma unroll
        for (int ni = 0; ni < 4; ni++) {
            int r0 = wm * 64 + mi * 16 + tq;
            int cc = wn * 32 + ni * 8 + tr2;
            *(float2*)&Ct[r0 * 132 + cc] =
                make_float2(acc[mi][ni][0] * alpha, acc[mi][ni][1] * alpha);
            *(float2*)&Ct[(r0 + 8) * 132 + cc] =
                make_float2(acc[mi][ni][2] * alpha, acc[mi][ni][3] * alpha);
        }
    __syncthreads();

#pragma unroll
    for (int it = 0; it < 16; it++) {
        int r = it * 8 + wid;
        float4 v = *(float4*)&Ct[r * 132 + lane * 4];
        if (OUTB) {
            __nv_bfloat16 h0 = __float2bfloat16(v.x), h1 = __float2bfloat16(v.y);
            __nv_bfloat16 h2 = __float2bfloat16(v.z), h3 = __float2bfloat16(v.w);
            long base = (long)(bm + r) * ldc + bn + lane * 4;
            ((__nv_bfloat162*)(Ch + base))[0] = __nv_bfloat162(h0, h1);
            ((__nv_bfloat162*)(Ch + base))[1] = __nv_bfloat162(h2, h3);
            ((__nv_bfloat162*)(Cl + base))[0] =
                __nv_bfloat162(__float2bfloat16(v.x - __bfloat162float(h0)),
                               __float2bfloat16(v.y - __bfloat162float(h1)));
            ((__nv_bfloat162*)(Cl + base))[1] =
                __nv_bfloat162(__float2bfloat16(v.z - __bfloat162float(h2)),
                               __float2bfloat16(v.w - __bfloat162float(h3)));
        } else {
            if (D) {
                // vectorized mask add: address provably 16B-aligned at all call sites
                float4 dv = *(const float4*)&D[(long)(bm + r) * ldd + bn + lane * 4];
                v.x += dv.x; v.y += dv.y; v.z += dv.z; v.w += dv.w;
            }
            *(float4*)&C[(long)(bm + r) * ldc + bn + lane * 4] = v;
        }
    }
}

// ---------------------------------------------------------------------------
// Multi-segment fp32 -> bf16 hi/lo split, MLP=4 per thread (one launch)
// ---------------------------------------------------------------------------
#define NSEG 10
struct CvtSegs {
    const float* x[NSEG];
    __nv_bfloat16* h[NSEG];
    __nv_bfloat16* l[NSEG];
    long start[NSEG + 1];     // prefix sums in float4 units
};

__global__ void cvt_multi_kernel(CvtSegs s)
{
    long base = (long)blockIdx.x * 1024 + threadIdx.x;
#pragma unroll
    for (int u = 0; u < 4; u++) {
        long i = base + u * 256;
        if (i >= s.start[NSEG]) return;
        int seg = 0;
#pragma unroll
        for (int j = 1; j < NSEG; j++) seg += (i >= s.start[j]);
        long off = i - s.start[seg];

        float4 v = ((const float4*)s.x[seg])[off];
        __nv_bfloat16 h0 = __float2bfloat16(v.x), h1 = __float2bfloat16(v.y);
        __nv_bfloat16 h2 = __float2bfloat16(v.z), h3 = __float2bfloat16(v.w);
        ((__nv_bfloat162*)s.h[seg])[off * 2 + 0] = __nv_bfloat162(h0, h1);
        ((__nv_bfloat162*)s.h[seg])[off * 2 + 1] = __nv_bfloat162(h2, h3);
        ((__nv_bfloat162*)s.l[seg])[off * 2 + 0] =
            __nv_bfloat162(__float2bfloat16(v.x - __bfloat162float(h0)),
                           __float2bfloat16(v.y - __bfloat162float(h1)));
        ((__nv_bfloat162*)s.l[seg])[off * 2 + 1] =
            __nv_bfloat162(__float2bfloat16(v.z - __bfloat162float(h2)),
                           __float2bfloat16(v.w - __bfloat162float(h3)));
    }
}

// ---------------------------------------------------------------------------
// Fused prep: RoPE+split (q,k) AND V-transpose+split, one launch.
// Blocks [0, ROPE_BLKS): RoPE.  Blocks [ROPE_BLKS, ROPE_BLKS+VT_BLKS): vtrans.
// ---------------------------------------------------------------------------
#define ROPE_BLKS 9216      // (B*Lc*12*32) / 256
#define VT_BLKS   3072      // (DHc/32) * (Lc/64) * (B*HKVc) = 8*24*16

__global__ void prep_kernel(const float* __restrict__ qkv,
                            const float* __restrict__ cosp, const float* __restrict__ sinp,
                            __nv_bfloat16* __restrict__ qh, __nv_bfloat16* __restrict__ ql,
                            __nv_bfloat16* __restrict__ kh, __nv_bfloat16* __restrict__ kl,
                            __nv_bfloat16* __restrict__ vh, __nv_bfloat16* __restrict__ vl)
{
    __shared__ float ts[64][33];
    int blk = blockIdx.x;
    int tid = threadIdx.x;

    if (blk < ROPE_BLKS) {
        // ---------------- RoPE + split (vectorized x4) ----------------
        long idx = (long)blk * 256 + tid;
        int  d   = (int)(idx & 31) * 4;
        long t   = idx >> 5;
        int  h12 = (int)(t % 12);
        long bl  = t / 12;

        float4 c4 = *(const float4*)&cosp[bl * 128 + d];
        float4 s4 = *(const float4*)&sinp[bl * 128 + d];

        const float* row = qkv + bl * QKVW;
        __nv_bfloat16 *dh, *dl;
        int colbase;
        if (h12 < 8) {
            colbase = h12 * DHc;
            long dbase = bl * (Hc * DHc) + h12 * DHc;
            dh = qh + dbase; dl = ql + dbase;
        } else {
            colbase = 2048 + (h12 - 8) * DHc;
            long dbase = bl * (HKVc * DHc) + (h12 - 8) * DHc;
            dh = kh + dbase; dl = kl + dbase;
        }
        float4 x1 = *(const float4*)&row[colbase + d];
        float4 x2 = *(const float4*)&row[colbase + d + 128];

        float o1x = x1.x * c4.x - x2.x * s4.x,  o2x = x2.x * c4.x + x1.x * s4.x;
        float o1y = x1.y * c4.y - x2.y * s4.y,  o2y = x2.y * c4.y + x1.y * s4.y;
        float o1z = x1.z * c4.z - x2.z * s4.z,  o2z = x2.z * c4.z + x1.z * s4.z;
        float o1w = x1.w * c4.w - x2.w * s4.w,  o2w = x2.w * c4.w + x1.w * s4.w;

        __nv_bfloat16 a0 = __float2bfloat16(o1x), a1 = __float2bfloat16(o1y);
        __nv_bfloat16 a2 = __float2bfloat16(o1z), a3 = __float2bfloat16(o1w);
        __nv_bfloat16 b0 = __float2bfloat16(o2x), b1 = __float2bfloat16(o2y);
        __nv_bfloat16 b2 = __float2bfloat16(o2z), b3 = __float2bfloat16(o2w);

        ((__nv_bfloat162*)(dh + d))[0]       = __nv_bfloat162(a0, a1);
        ((__nv_bfloat162*)(dh + d))[1]       = __nv_bfloat162(a2, a3);
        ((__nv_bfloat162*)(dh + d + 128))[0] = __nv_bfloat162(b0, b1);
        ((__nv_bfloat162*)(dh + d + 128))[1] = __nv_bfloat162(b2, b3);

        ((__nv_bfloat162*)(dl + d))[0] =
            __nv_bfloat162(__float2bfloat16(o1x - __bfloat162float(a0)),
                           __float2bfloat16(o1y - __bfloat162float(a1)));
        ((__nv_bfloat162*)(dl + d))[1] =
            __nv_bfloat162(__float2bfloat16(o1z - __bfloat162float(a2)),
                           __float2bfloat16(o1w - __bfloat162float(a3)));
        ((__nv_bfloat162*)(dl + d + 128))[0] =
            __nv_bfloat162(__float2bfloat16(o2x - __bfloat162float(b0)),
                           __float2bfloat16(o2y - __bfloat162float(b1)));
        ((__nv_bfloat162*)(dl + d + 128))[1] =
            __nv_bfloat162(__float2bfloat16(o2z - __bfloat162float(b2)),
                           __float2bfloat16(o2w - __bfloat162float(b3)));
    } else {
        // ---------------- V transpose + split ----------------
        int f = blk - ROPE_BLKS;
        int bx = f & 7;              // DHc/32 = 8
        int rem = f >> 3;
        int by = rem % 24;           // Lc/64 = 24
        int z  = rem / 24;           // B*HKV = 16

        const float* src = qkv + (long)(z / HKVc) * Lc * QKVW + 3072 + (z % HKVc) * DHc;
        __nv_bfloat16* dh = vh + (long)z * DHc * Lc;
        __nv_bfloat16* dl = vl + (long)z * DHc * Lc;
        int l0 = by * 64, d0 = bx * 32;
        int tx = tid & 31, ty = tid >> 5;   // (32, 8)
#pragma unroll
        for (int j = 0; j < 8; j++)
            ts[ty + j * 8][tx] = src[(long)(l0 + ty + j * 8) * QKVW + d0 + tx];
        __syncthreads();
#pragma unroll
        for (int j = 0; j < 4; j++) {
            int d  = d0 + ty + j * 8;
            int dy = ty + j * 8;
            float va = ts[tx * 2][dy], vb = ts[tx * 2 + 1][dy];
            __nv_bfloat16 ha = __float2bfloat16(va), hb = __float2bfloat16(vb);
            ((__nv_bfloat162*)&dh[(long)d * Lc + l0])[tx] = __nv_bfloat162(ha, hb);
            ((__nv_bfloat162*)&dl[(long)d * Lc + l0])[tx] =
                __nv_bfloat162(__float2bfloat16(va - __bfloat162float(ha)),
                               __float2bfloat16(vb - __bfloat162float(hb)));
        }
    }
}

// ---------------------------------------------------------------------------
// Register-resident softmax + bf16 hi/lo split (384 threads/row, L=1536)
// ---------------------------------------------------------------------------
__global__ void __launch_bounds__(384, 4) softmax_cvt_kernel(
    const float* __restrict__ S,
    __nv_bfloat16* __restrict__ ph, __nv_bfloat16* __restrict__ pl)
{
    long row = blockIdx.x;
    int  tid = threadIdx.x;
    int  wrp = tid >> 5, ln = tid & 31;
    __shared__ float red[12];

    float4 v = ((const float4*)(S + row * (long)Lc))[tid];

    float mx = fmaxf(fmaxf(v.x, v.y), fmaxf(v.z, v.w));
#pragma unroll
    for (int o = 16; o > 0; o >>= 1)
        mx = fmaxf(mx, __shfl_xor_sync(0xffffffffu, mx, o));
    if (ln == 0) red[wrp] = mx;
    __syncthreads();
    if (tid < 32) {
        float m2 = (tid < 12) ? red[tid] : -INFINITY;
#pragma unroll
        for (int o = 16; o > 0; o >>= 1)
            m2 = fmaxf(m2, __shfl_xor_sync(0xffffffffu, m2, o));
        if (tid == 0) red[0] = m2;
    }
    __syncthreads();
    mx = red[0];
    __syncthreads();

    float e0 = __expf(v.x - mx), e1 = __expf(v.y - mx);
    float e2 = __expf(v.z - mx), e3 = __expf(v.w - mx);

    float sm = (e0 + e1) + (e2 + e3);
#pragma unroll
    for (int o = 16; o > 0; o >>= 1)
        sm += __shfl_xor_sync(0xffffffffu, sm, o);
    if (ln == 0) red[wrp] = sm;
    __syncthreads();
    if (tid < 32) {
        float s2 = (tid < 12) ? red[tid] : 0.f;
#pragma unroll
        for (int o = 16; o > 0; o >>= 1)
            s2 += __shfl_xor_sync(0xffffffffu, s2, o);
        if (tid == 0) red[0] = s2;
    }
    __syncthreads();
    float inv = 1.f / red[0];

    e0 *= inv; e1 *= inv; e2 *= inv; e3 *= inv;
    __nv_bfloat16 h0 = __float2bfloat16(e0), h1 = __float2bfloat16(e1);
    __nv_bfloat16 h2 = __float2bfloat16(e2), h3 = __float2bfloat16(e3);
    long base2 = row * (long)(Lc / 2) + tid * 2;
    ((__nv_bfloat162*)ph)[base2]     = __nv_bfloat162(h0, h1);
    ((__nv_bfloat162*)ph)[base2 + 1] = __nv_bfloat162(h2, h3);
    ((__nv_bfloat162*)pl)[base2] =
        __nv_bfloat162(__float2bfloat16(e0 - __bfloat162float(h0)),
                       __float2bfloat16(e1 - __bfloat162float(h1)));
    ((__nv_bfloat162*)pl)[base2 + 1] =
        __nv_bfloat162(__float2bfloat16(e2 - __bfloat162float(h2)),
                       __float2bfloat16(e3 - __bfloat162float(h3)));
}

// ---------------------------------------------------------------------------
// Host side
// ---------------------------------------------------------------------------
static inline void run_gemm(const __nv_bfloat16* Ah, const __nv_bfloat16* Al,
                            const __nv_bfloat16* Bh, const __nv_bfloat16* Bl,
                            float* C, const float* D,
                            int M, int N, int K, int lda, int ldb, int ldc, int ldd,
                            long sAo, long sAi, long sBo, long sBi,
                            long sCo, long sCi, long sDo,
                            int nb, int dv, int rep, float alpha)
{
    dim3 grid(N / 128, M / 128, nb);
    gemm_mma<0><<<grid, 256, SMEM_BYTES>>>(Ah, Al, Bh, Bl, C, D, nullptr, nullptr,
                                           M, N, K, lda, ldb, ldc, ldd,
                                           sAo, sAi, sBo, sBi, sCo, sCi, sDo,
                                           dv, rep, alpha);
}

static inline void run_gemm_b16(const __nv_bfloat16* Ah, const __nv_bfloat16* Al,
                                const __nv_bfloat16* Bh, const __nv_bfloat16* Bl,
                                __nv_bfloat16* Ch, __nv_bfloat16* Cl,
                                int M, int N, int K, int lda, int ldb, int ldc,
                                long sAo, long sAi, long sBo, long sBi,
                                long sCo, long sCi,
                                int nb, int dv, int rep, float alpha)
{
    dim3 grid(N / 128, M / 128, nb);
    gemm_mma<1><<<grid, 256, SMEM_BYTES>>>(Ah, Al, Bh, Bl, nullptr, nullptr, Ch, Cl,
                                           M, N, K, lda, ldb, ldc, 0,
                                           sAo, sAi, sBo, sBi, sCo, sCi, 0,
                                           dv, rep, alpha);
}

extern "C" void kernel_launch(void* const* d_in, const int* in_sizes, int n_in,
                              void* d_out, int out_size)
{
    const float* pg   = (const float*)d_in[0];
    const float* ex   = (const float*)d_in[1];
    const float* cosp = (const float*)d_in[2];
    const float* sinp = (const float*)d_in[3];
    const float* mask = (const float*)d_in[4];
    const float* W[8] = { (const float*)d_in[5],  (const float*)d_in[6],
                          (const float*)d_in[7],  (const float*)d_in[8],
                          (const float*)d_in[9],  (const float*)d_in[10],
                          (const float*)d_in[11], (const float*)d_in[12] };
    float* out = (float*)d_out;

    cudaFuncSetAttribute(gemm_mma<0>, cudaFuncAttributeMaxDynamicSharedMemorySize, SMEM_BYTES);
    cudaFuncSetAttribute(gemm_mma<1>, cudaFuncAttributeMaxDynamicSharedMemorySize, SMEM_BYTES);

    float *qkv, *sc;
    cudaGetSymbolAddress((void**)&qkv, g_qkv);
    cudaGetSymbolAddress((void**)&sc,  g_scores);

#define GETHL(sym, hp, lp) \
    __nv_bfloat16 *hp, *lp; \
    cudaGetSymbolAddress((void**)&hp, sym##_h); \
    cudaGetSymbolAddress((void**)&lp, sym##_l);

    GETHL(g_pg,  pgh,  pgl)   GETHL(g_ex,  exh,  exl)
    GETHL(g_wc0, wc0h, wc0l)  GETHL(g_wc1, wc1h, wc1l)
    GETHL(g_wo0, wo0h, wo0l)  GETHL(g_wo1, wo1h, wo1l)
    GETHL(g_qb,  qh,   ql)    GETHL(g_kb,  kh,   kl)
    GETHL(g_vt,  vth,  vtl)   GETHL(g_p,   pph,  ppl)
    GETHL(g_attb, atth, attl)

    const int HD  = Hc * DHc;     // 2048
    const int KVD = HKVc * DHc;   // 1024

    // --- all input/weight splits in ONE launch (MLP=4 per thread) ---
    {
        CvtSegs s;
        const float* xs[NSEG] = { pg, ex, W[0], W[1], W[2], W[4], W[5], W[6], W[3], W[7] };
        __nv_bfloat16* hs[NSEG] = {
            pgh, exh,
            wc0h, wc0h + (long)2048 * DPGc, wc0h + (long)3072 * DPGc,
            wc1h, wc1h + (long)2048 * DEXc, wc1h + (long)3072 * DEXc,
            wo0h, wo1h };
        __nv_bfloat16* ls[NSEG] = {
            pgl, exl,
            wc0l, wc0l + (long)2048 * DPGc, wc0l + (long)3072 * DPGc,
            wc1l, wc1l + (long)2048 * DEXc, wc1l + (long)3072 * DEXc,
            wo0l, wo1l };
        long ns[NSEG] = {
            (long)Bc * L1c * DPGc, (long)Bc * L2c * DEXc,
            (long)HD * DPGc, (long)KVD * DPGc, (long)KVD * DPGc,
            (long)HD * DEXc, (long)KVD * DEXc, (long)KVD * DEXc,
            (long)DPGc * HD, (long)DEXc * HD };
        s.start[0] = 0;
        for (int i = 0; i < NSEG; i++) {
            s.x[i] = xs[i]; s.h[i] = hs[i]; s.l[i] = ls[i];
            s.start[i + 1] = s.start[i] + (ns[i] >> 2);
        }
        long tot = s.start[NSEG];
        cvt_multi_kernel<<<(int)((tot + 1023) / 1024), 256>>>(s);
    }

    // --- fused QKV projections (2 launches, dim3 grids) ---
    run_gemm(pgh, pgl, wc0h, wc0l, qkv, nullptr, L1c, QKVW, DPGc,
             DPGc, DPGc, QKVW, 0,
             (long)L1c * DPGc, 0, 0, 0, (long)Lc * QKVW, 0, 0, Bc, 1, 1, 1.0f);
    run_gemm(exh, exl, wc1h, wc1l, qkv + (long)L1c * QKVW, nullptr, L2c, QKVW, DEXc,
             DEXc, DEXc, QKVW, 0,
             (long)L2c * DEXc, 0, 0, 0, (long)Lc * QKVW, 0, 0, Bc, 1, 1, 1.0f);

    // --- fused RoPE(q,k) + V-transpose in ONE launch ---
    prep_kernel<<<ROPE_BLKS + VT_BLKS, 256>>>(qkv, cosp, sinp,
                                              qh, ql, kh, kl, vth, vtl);

    // --- scores = q @ k^T * SCALE + mask  [B*H batches, GQA rep=2] ---
    run_gemm(qh, ql, kh, kl, sc, mask, Lc, Lc, DHc,
             HD, KVD, Lc, Lc,
             (long)Lc * HD, DHc,
             (long)Lc * KVD, DHc,
             (long)Hc * Lc * Lc, (long)Lc * Lc,
             (long)Lc * Lc,
             Bc * Hc, Hc, 2, SCALEc);

    // --- softmax + split (register-resident, single pass) ---
    softmax_cvt_kernel<<<Bc * Hc * Lc, 384>>>(sc, pph, ppl);

    // --- att = P @ V^T, writing bf16 hi/lo directly (fused epilogue) ---
    run_gemm_b16(pph, ppl, vth, vtl, atth, attl, Lc, DHc, Lc,
                 Lc, Lc, HD,
                 (long)Hc * Lc * Lc, (long)Lc * Lc,
                 (long)HKVc * DHc * Lc, (long)DHc * Lc,
                 (long)Lc * HD, DHc,
                 Bc * Hc, Hc, 2, 1.0f);

    // --- output projections ---
    run_gemm(atth, attl, wo0h, wo0l, out, nullptr, L1c, DPGc, HD,
             HD, HD, DPGc, 0,
             (long)Lc * HD, 0, 0, 0,
             (long)L1c * DPGc, 0, 0, Bc, 1, 1, 1.0f);
    run_gemm(atth + (long)L1c * HD, attl + (long)L1c * HD, wo1h, wo1l,
             out + (long)Bc * L1c * DPGc, nullptr, L2c, DEXc, HD,
             HD, HD, DEXc, 0,
             (long)Lc * HD, 0, 0, 0,
             (long)L2c * DEXc, 0, 0, Bc, 1, 1, 1.0f);
}